// round 16
// baseline (speedup 1.0000x reference)
#include <cuda_runtime.h>
#include <cuda_fp16.h>
#include <cstdint>
#include <math.h>

#define BATCH 16384
#define DIM   512
#define CLS   1024
#define INV_TAU 10.0f
#define TAU   0.1f
#define LCUT  20.0f      // survivors: logit > max - LCUT  (e > 2e-9)
#define CAP   128

// ============================ scratch (device globals) ============================
__device__ __half g_x16[BATCH * DIM];            // normalized x, fp16
__device__ __half g_p16[CLS * DIM];              // normalized p, fp16  [CLS][DIM]
__device__ float  g_logit[(size_t)BATCH * CLS];  // gumbel logits (sim+g)/tau (64 MB)
__device__ double g_colsum[DIM];
__device__ double g_acc[3];                      // 2: sum_b e.sim

__global__ void k_init() {
    int t = threadIdx.x;
    if (t < DIM) g_colsum[t] = 0.0;
    if (t < 3) g_acc[t] = 0.0;
}

// ---- row L2 normalize x -> fp16 ----
__global__ void k_norm_x(const float* __restrict__ in) {
    int row = blockIdx.x, t = threadIdx.x;
    float4 v = ((const float4*)(in + (size_t)row * DIM))[t];
    float ss = v.x * v.x + v.y * v.y + v.z * v.z + v.w * v.w;
    #pragma unroll
    for (int o = 16; o; o >>= 1) ss += __shfl_xor_sync(0xffffffffu, ss, o);
    __shared__ float w[4];
    if ((t & 31) == 0) w[t >> 5] = ss;
    __syncthreads();
    ss = w[0] + w[1] + w[2] + w[3];
    float inv = 1.0f / fmaxf(sqrtf(ss), 1e-12f);
    union { __half h[4]; uint2 u; } H;
    H.h[0] = __float2half(v.x * inv); H.h[1] = __float2half(v.y * inv);
    H.h[2] = __float2half(v.z * inv); H.h[3] = __float2half(v.w * inv);
    *(uint2*)(g_x16 + (size_t)row * DIM + 4 * t) = H.u;
}

// ---- normalize p -> fp32 output + fp16 ----
__global__ void k_norm_p(const float* __restrict__ in, float* __restrict__ outp) {
    int row = blockIdx.x, t = threadIdx.x;
    float4 v = ((const float4*)(in + (size_t)row * DIM))[t];
    float ss = v.x * v.x + v.y * v.y + v.z * v.z + v.w * v.w;
    #pragma unroll
    for (int o = 16; o; o >>= 1) ss += __shfl_xor_sync(0xffffffffu, ss, o);
    __shared__ float w[4];
    if ((t & 31) == 0) w[t >> 5] = ss;
    __syncthreads();
    ss = w[0] + w[1] + w[2] + w[3];
    float inv = 1.0f / fmaxf(sqrtf(ss), 1e-12f);
    float f[4] = {v.x * inv, v.y * inv, v.z * inv, v.w * inv};
    ((float4*)(outp + (size_t)row * DIM))[t] = make_float4(f[0], f[1], f[2], f[3]);
    union { __half h[4]; uint2 u; } H;
    #pragma unroll
    for (int i = 0; i < 4; i++) H.h[i] = __float2half(f[i]);
    *(uint2*)(g_p16 + (size_t)row * DIM + 4 * t) = H.u;
}

// ---- div_loss colsum (sum||p_k||^2 == 1024 after normalize). grid (4,64) ----
__global__ void k_proto_stats(const float* __restrict__ p) {
    int col = blockIdx.x * 128 + threadIdx.x;
    int r0 = blockIdx.y * 16;
    double sc = 0.0;
    #pragma unroll
    for (int r = 0; r < 16; r++)
        sc += (double)p[(size_t)(r0 + r) * DIM + col];
    atomicAdd(&g_colsum[col], sc);
}

// ============================ fp16 mma.sync GEMM + gumbel epilogue ============================
// 128x128 CTA tile, 4 warps (2x2), warp tile 64x64, BK=64, 2-stage cp.async.
// Mainloop frozen (fp32-accum HMMA ceiling). Epilogue computes gumbel logits on the
// idle MUFU pipe: logit = (sim + (-log(-log u))) * 10, stored to g_logit.
#define BM 128
#define BN 128
#define BK 64
#define NTHR 128
#define PADROW 72                    // row stride in halves (144 B): 36 words == 4 mod 32
#define MAT_BYTES (BM * PADROW * 2)  // 18432 B
#define GSMEM_SZ (4 * MAT_BYTES)     // 2 buffers x 2 matrices = 73728 B

#define MMA_F16(c, a, b) \
    asm volatile("mma.sync.aligned.m16n8k16.row.col.f32.f16.f16.f32 " \
        "{%0,%1,%2,%3}, {%4,%5,%6,%7}, {%8,%9}, {%0,%1,%2,%3};" \
        : "+f"((c)[0]), "+f"((c)[1]), "+f"((c)[2]), "+f"((c)[3]) \
        : "r"((a)[0]), "r"((a)[1]), "r"((a)[2]), "r"((a)[3]), \
          "r"((b)[0]), "r"((b)[1]))

#define LDSM_X4(r, addr) \
    asm volatile("ldmatrix.sync.aligned.m8n8.x4.shared.b16 {%0,%1,%2,%3}, [%4];" \
        : "=r"((r)[0]), "=r"((r)[1]), "=r"((r)[2]), "=r"((r)[3]) : "r"(addr))

#define CP_ASYNC16(dst, src) \
    asm volatile("cp.async.cg.shared.global [%0], [%1], 16;" :: "r"(dst), "l"(src))
#define CP_COMMIT() asm volatile("cp.async.commit_group;" ::: "memory")
#define CP_WAIT(N)  asm volatile("cp.async.wait_group %0;" :: "n"(N) : "memory")

__device__ __forceinline__ float gumbel_of(float uv) {
    return -__logf(-__logf(uv));
}

__global__ __launch_bounds__(NTHR, 2) void k_gemm_sim(const float* __restrict__ U) {
    constexpr int Kd = 512, Nc = 1024, NCH = Kd / BK;
    const __half* __restrict__ pA = g_x16;
    const __half* __restrict__ pB = g_p16;
    float* __restrict__ C = g_logit;

    extern __shared__ __align__(16) char smem[];
    uint32_t sb = (uint32_t)__cvta_generic_to_shared(smem);
    #define SOFF(b, i) ((b) * 2 * MAT_BYTES + (i) * MAT_BYTES)

    int tid = threadIdx.x, lane = tid & 31, wid = tid >> 5;
    int warp_m = wid & 1, warp_n = wid >> 1;
    int m0 = blockIdx.y * BM, n0 = blockIdx.x * BN;

    float acc[4][8][4];
    #pragma unroll
    for (int i = 0; i < 4; i++)
        #pragma unroll
        for (int j = 0; j < 8; j++)
            #pragma unroll
            for (int q = 0; q < 4; q++) acc[i][j][q] = 0.0f;

    int la = (lane & 15) * PADROW + ((lane >> 4) << 3);
    int lb = (((lane >> 4) << 3) + (lane & 7)) * PADROW + (((lane >> 3) & 1) << 3);

    #define ISSUE_CHUNK(ch, b) do { \
        _Pragma("unroll") \
        for (int l = 0; l < 8; l++) { \
            int idx = tid + l * NTHR; \
            int r = idx >> 3, ko = (idx & 7) * 8; \
            size_t ga = (size_t)(m0 + r) * Kd + (ch) * BK + ko; \
            size_t gb = (size_t)(n0 + r) * Kd + (ch) * BK + ko; \
            uint32_t so = (uint32_t)((r * PADROW + ko) * 2); \
            CP_ASYNC16(sb + SOFF(b, 0) + so, pA + ga); \
            CP_ASYNC16(sb + SOFF(b, 1) + so, pB + gb); \
        } \
        CP_COMMIT(); } while (0)

    ISSUE_CHUNK(0, 0);

    #pragma unroll 1
    for (int ch = 0; ch < NCH; ch++) {
        int b = ch & 1;
        if (ch + 1 < NCH) { ISSUE_CHUNK(ch + 1, b ^ 1); CP_WAIT(1); }
        else              { CP_WAIT(0); }
        __syncthreads();

        uint32_t uA = sb + SOFF(b, 0), uB = sb + SOFF(b, 1);

        #pragma unroll
        for (int kk = 0; kk < 4; kk++) {
            int kb = kk * 16;
            uint32_t a[4][4], bfr[4][4];
            #pragma unroll
            for (int mt = 0; mt < 4; mt++) {
                uint32_t ao = 2u * ((warp_m * 64 + mt * 16) * PADROW + la + kb);
                LDSM_X4(a[mt], uA + ao);
            }
            #pragma unroll
            for (int p = 0; p < 4; p++) {
                uint32_t bo = 2u * ((warp_n * 64 + p * 16) * PADROW + lb + kb);
                LDSM_X4(bfr[p], uB + bo);
            }
            #pragma unroll
            for (int mt = 0; mt < 4; mt++)
                #pragma unroll
                for (int nt = 0; nt < 8; nt++)
                    MMA_F16(acc[mt][nt], a[mt], &bfr[nt >> 1][(nt & 1) * 2]);
        }

        if (ch + 1 < NCH) __syncthreads();
    }

    // epilogue: logits = (sim + gumbel(u)) * INV_TAU  (MUFU pipe is idle here)
    #pragma unroll
    for (int mt = 0; mt < 4; mt++) {
        int row = m0 + warp_m * 64 + mt * 16 + (lane >> 2);
        #pragma unroll
        for (int nt = 0; nt < 8; nt++) {
            int col = n0 + warp_n * 64 + nt * 8 + (lane & 3) * 2;
            float2 u0 = *(const float2*)(U + (size_t)row * Nc + col);
            float2 u1 = *(const float2*)(U + (size_t)(row + 8) * Nc + col);
            *(float2*)(C + (size_t)row * Nc + col) = make_float2(
                (acc[mt][nt][0] + gumbel_of(u0.x)) * INV_TAU,
                (acc[mt][nt][1] + gumbel_of(u0.y)) * INV_TAU);
            *(float2*)(C + (size_t)(row + 8) * Nc + col) = make_float2(
                (acc[mt][nt][2] + gumbel_of(u1.x)) * INV_TAU,
                (acc[mt][nt][3] + gumbel_of(u1.y)) * INV_TAU);
        }
    }
    #undef SOFF
}

// ============ sparse softmax + pt from precomputed logits (near-MUFU-free) ============
// One block (256 thr) per row. Bulk pass: load logits, row max, stage to smem —
// compares only. Survivors (logit > max-LCUT, e > 2e-9) compacted; warp 0 computes
// their exps, the sum (dropped mass <= 2e-6 rel), and the dot, recovering
// sim = TAU*logit - gumbel(u) for survivors only. pt = sum w_k p16[k] over survivors.
// Overflow (>CAP) falls back to the exact full-row path (data-deterministic).
__global__ __launch_bounds__(256) void k_softmax_pt(const float* __restrict__ u,
                                                    float* __restrict__ out_pt) {
    int row = blockIdx.x, t = threadIdx.x, lane = t & 31, wid = t >> 5;
    size_t base = (size_t)row * CLS;

    __shared__ float  s_l[CLS];
    __shared__ unsigned short s_idx[CAP];
    __shared__ float  s_e[CAP];
    __shared__ float  red[8];
    __shared__ float  red2[8][2];
    __shared__ int    s_wbase[8], s_total;
    __shared__ float  s_sd[2];

    float4 l4 = ((const float4*)(g_logit + base))[t];
    *(float4*)(s_l + 4 * t) = l4;
    float l[4] = {l4.x, l4.y, l4.z, l4.w};

    float mx = fmaxf(fmaxf(l[0], l[1]), fmaxf(l[2], l[3]));
    #pragma unroll
    for (int o = 16; o; o >>= 1) mx = fmaxf(mx, __shfl_xor_sync(0xffffffffu, mx, o));
    if (lane == 0) red[wid] = mx;
    __syncthreads();                                     // bar 1: max + s_l ready
    mx = red[0];
    #pragma unroll
    for (int i = 1; i < 8; i++) mx = fmaxf(mx, red[i]);
    float cut = mx - LCUT;

    // compact survivor indices (logit > cut) via warp scan
    int c = (l[0] > cut) + (l[1] > cut) + (l[2] > cut) + (l[3] > cut);
    int sc = c;
    #pragma unroll
    for (int o = 1; o < 32; o <<= 1) {
        int v = __shfl_up_sync(0xffffffffu, sc, o);
        if (lane >= o) sc += v;
    }
    int excl = sc - c;
    if (lane == 31) s_wbase[wid] = sc;
    __syncthreads();                                     // bar 2
    if (t == 0) {
        int run = 0;
        #pragma unroll
        for (int i = 0; i < 8; i++) { int v = s_wbase[i]; s_wbase[i] = run; run += v; }
        s_total = run;
    }
    __syncthreads();                                     // bar 3
    int total = s_total;

    if (total <= CAP) {
        int pos = s_wbase[wid] + excl;
        #pragma unroll
        for (int i = 0; i < 4; i++)
            if (l[i] > cut) s_idx[pos++] = (unsigned short)(4 * t + i);
        __syncthreads();                                 // bar 4: idx ready

        // warp 0: exps + sum + dot over survivors (sim recovered from u)
        if (wid == 0) {
            float ps = 0.f, pd = 0.f;
            for (int j = lane; j < total; j += 32) {
                int k = s_idx[j];
                float lv = s_l[k];
                float ev = __expf(lv - mx);
                s_e[j] = ev;
                float g = gumbel_of(u[base + k]);
                ps += ev;
                pd += ev * (TAU * lv - g);
            }
            #pragma unroll
            for (int o = 16; o; o >>= 1) {
                ps += __shfl_xor_sync(0xffffffffu, ps, o);
                pd += __shfl_xor_sync(0xffffffffu, pd, o);
            }
            if (lane == 0) { s_sd[0] = ps; s_sd[1] = pd; }
        }
        __syncthreads();                                 // bar 5: e/sum/dot ready

        float inv = 1.0f / s_sd[0];
        float ax = 0.f, ay = 0.f;
        int c2 = 2 * t;
        #pragma unroll 2
        for (int j = 0; j < total; j++) {
            float wv = s_e[j];
            int k = s_idx[j];
            __half2 pv = *(const __half2*)(g_p16 + (size_t)k * DIM + c2);
            float2 pf = __half22float2(pv);
            ax += wv * pf.x; ay += wv * pf.y;
        }
        *(float2*)(out_pt + (size_t)row * DIM + c2) = make_float2(ax * inv, ay * inv);

        if (t == 0) atomicAdd(&g_acc[2], (double)(s_sd[1] / s_sd[0]));
    } else {
        // fallback: exact full-row softmax (rare; deterministic in data)
        float4 u4 = ((const float4*)(u + base))[t];
        float e[4], sim[4];
        float gv[4] = {gumbel_of(u4.x), gumbel_of(u4.y), gumbel_of(u4.z), gumbel_of(u4.w)};
        #pragma unroll
        for (int i = 0; i < 4; i++) {
            e[i] = __expf(l[i] - mx);
            sim[i] = TAU * l[i] - gv[i];
        }
        float sum = e[0] + e[1] + e[2] + e[3];
        float dot = e[0] * sim[0] + e[1] * sim[1] + e[2] * sim[2] + e[3] * sim[3];
        #pragma unroll
        for (int o = 16; o; o >>= 1) {
            sum += __shfl_xor_sync(0xffffffffu, sum, o);
            dot += __shfl_xor_sync(0xffffffffu, dot, o);
        }
        if (lane == 0) { red2[wid][0] = sum; red2[wid][1] = dot; }
        __syncthreads();
        float tsum = 0.f, tdot = 0.f;
        #pragma unroll
        for (int i = 0; i < 8; i++) { tsum += red2[i][0]; tdot += red2[i][1]; }
        float inv = 1.0f / tsum;
        // overwrite s_l with normalized weights
        *(float4*)(s_l + 4 * t) = make_float4(e[0] * inv, e[1] * inv, e[2] * inv, e[3] * inv);
        __syncthreads();
        float ax = 0.f, ay = 0.f;
        int c2 = 2 * t;
        #pragma unroll 4
        for (int k = 0; k < CLS; k++) {
            float wv = s_l[k];
            __half2 pv = *(const __half2*)(g_p16 + (size_t)k * DIM + c2);
            float2 pf = __half22float2(pv);
            ax += wv * pf.x; ay += wv * pf.y;
        }
        *(float2*)(out_pt + (size_t)row * DIM + c2) = make_float2(ax, ay);
        if (t == 0) atomicAdd(&g_acc[2], (double)(tdot * inv));
    }
}

// ---- finalize: div_loss = ||sum_k p_k||^2 - 1024 (rows are unit-norm) ----
__global__ void k_finalize(float* __restrict__ outs) {
    int t = threadIdx.x;                   // 512 threads = one column each
    double cs = g_colsum[t];
    double v = cs * cs;
    #pragma unroll
    for (int o = 16; o; o >>= 1) v += __shfl_xor_sync(0xffffffffu, v, o);
    __shared__ double sm[16];
    if ((t & 31) == 0) sm[t >> 5] = v;
    __syncthreads();
    if (t < 32) {
        double x = (t < 16) ? sm[t] : 0.0;
        #pragma unroll
        for (int o = 16; o; o >>= 1) x += __shfl_xor_sync(0xffffffffu, x, o);
        if (t == 0) {
            outs[0] = (float)(1.0 - g_acc[2] / (double)BATCH);  // sim_loss
            outs[1] = (float)(x - (double)CLS);                 // div_loss
        }
    }
}

extern "C" void kernel_launch(void* const* d_in, const int* in_sizes, int n_in,
                              void* d_out, int out_size) {
    const float* input  = (const float*)d_in[0];   // [16384, 512]
    const float* protos = (const float*)d_in[1];   // [1024, 512]
    const float* gu     = (const float*)d_in[2];   // [16384, 1024]
    float* out = (float*)d_out;
    float* out_pt = out;                                            // [16384, 512]
    float* out_p  = out + (size_t)BATCH * DIM;                      // [1024, 512]
    float* out_sc = out + (size_t)BATCH * DIM + (size_t)CLS * DIM;  // 2 scalars

    cudaFuncSetAttribute(k_gemm_sim, cudaFuncAttributeMaxDynamicSharedMemorySize, GSMEM_SZ);

    k_init<<<1, 512>>>();
    k_norm_x<<<BATCH, 128>>>(input);
    k_norm_p<<<CLS, 128>>>(protos, out_p);
    k_proto_stats<<<dim3(4, 64), 128>>>(out_p);
    k_gemm_sim<<<dim3(CLS / BN, BATCH / BM), NTHR, GSMEM_SZ>>>(gu);  // sim+gumbel -> logits
    k_softmax_pt<<<BATCH, 256>>>(gu, out_pt);                        // sparse softmax + pt
    k_finalize<<<1, 512>>>(out_sc);
}

// round 17
// speedup vs baseline: 1.1844x; 1.1844x over previous
#include <cuda_runtime.h>
#include <cuda_fp16.h>
#include <cstdint>
#include <math.h>

#define BATCH 16384
#define DIM   512
#define CLS   1024
#define INV_TAU 10.0f
#define WTH   1e-7f
#define CAP   128

// ============================ scratch (device globals) ============================
__device__ __half g_x16[BATCH * DIM];          // normalized x, fp16
__device__ __half g_p16[CLS * DIM];            // normalized p, fp16  [CLS][DIM]
__device__ float  g_sim[(size_t)BATCH * CLS];  // sim fp32 (64 MB)
__device__ double g_colsum[DIM];
__device__ double g_acc[3];                    // 2: sum_b e.sim

// ---- row L2 normalize x -> fp16 (block 0 also zeroes the scalar scratch) ----
__global__ void k_norm_x(const float* __restrict__ in) {
    int row = blockIdx.x, t = threadIdx.x;
    if (row == 0) {                    // init fold: colsum + acc (consumers launch later)
        #pragma unroll
        for (int i = 0; i < 4; i++) g_colsum[t + 128 * i] = 0.0;
        if (t < 3) g_acc[t] = 0.0;
    }
    float4 v = ((const float4*)(in + (size_t)row * DIM))[t];
    float ss = v.x * v.x + v.y * v.y + v.z * v.z + v.w * v.w;
    #pragma unroll
    for (int o = 16; o; o >>= 1) ss += __shfl_xor_sync(0xffffffffu, ss, o);
    __shared__ float w[4];
    if ((t & 31) == 0) w[t >> 5] = ss;
    __syncthreads();
    ss = w[0] + w[1] + w[2] + w[3];
    float inv = 1.0f / fmaxf(sqrtf(ss), 1e-12f);
    union { __half h[4]; uint2 u; } H;
    H.h[0] = __float2half(v.x * inv); H.h[1] = __float2half(v.y * inv);
    H.h[2] = __float2half(v.z * inv); H.h[3] = __float2half(v.w * inv);
    *(uint2*)(g_x16 + (size_t)row * DIM + 4 * t) = H.u;
}

// ---- normalize p -> fp32 output + fp16 ----
__global__ void k_norm_p(const float* __restrict__ in, float* __restrict__ outp) {
    int row = blockIdx.x, t = threadIdx.x;
    float4 v = ((const float4*)(in + (size_t)row * DIM))[t];
    float ss = v.x * v.x + v.y * v.y + v.z * v.z + v.w * v.w;
    #pragma unroll
    for (int o = 16; o; o >>= 1) ss += __shfl_xor_sync(0xffffffffu, ss, o);
    __shared__ float w[4];
    if ((t & 31) == 0) w[t >> 5] = ss;
    __syncthreads();
    ss = w[0] + w[1] + w[2] + w[3];
    float inv = 1.0f / fmaxf(sqrtf(ss), 1e-12f);
    float f[4] = {v.x * inv, v.y * inv, v.z * inv, v.w * inv};
    ((float4*)(outp + (size_t)row * DIM))[t] = make_float4(f[0], f[1], f[2], f[3]);
    union { __half h[4]; uint2 u; } H;
    #pragma unroll
    for (int i = 0; i < 4; i++) H.h[i] = __float2half(f[i]);
    *(uint2*)(g_p16 + (size_t)row * DIM + 4 * t) = H.u;
}

// ---- div_loss colsum (sum||p_k||^2 == 1024 after normalize). grid (4,64) ----
__global__ void k_proto_stats(const float* __restrict__ p) {
    int col = blockIdx.x * 128 + threadIdx.x;
    int r0 = blockIdx.y * 16;
    double sc = 0.0;
    #pragma unroll
    for (int r = 0; r < 16; r++)
        sc += (double)p[(size_t)(r0 + r) * DIM + col];
    atomicAdd(&g_colsum[col], sc);
}

// ============================ fp16 mma.sync GEMM (sim only) ============================
// 128x128 CTA tile, 4 warps (2x2), warp tile 64x64, BK=64, 2-stage cp.async.
// Measured 52.8us @ tensor=53.5% across 3 configs = fp32-accum HMMA ceiling. Frozen.
#define BM 128
#define BN 128
#define BK 64
#define NTHR 128
#define PADROW 72                    // row stride in halves (144 B): 36 words == 4 mod 32
#define MAT_BYTES (BM * PADROW * 2)  // 18432 B
#define GSMEM_SZ (4 * MAT_BYTES)     // 2 buffers x 2 matrices = 73728 B

#define MMA_F16(c, a, b) \
    asm volatile("mma.sync.aligned.m16n8k16.row.col.f32.f16.f16.f32 " \
        "{%0,%1,%2,%3}, {%4,%5,%6,%7}, {%8,%9}, {%0,%1,%2,%3};" \
        : "+f"((c)[0]), "+f"((c)[1]), "+f"((c)[2]), "+f"((c)[3]) \
        : "r"((a)[0]), "r"((a)[1]), "r"((a)[2]), "r"((a)[3]), \
          "r"((b)[0]), "r"((b)[1]))

#define LDSM_X4(r, addr) \
    asm volatile("ldmatrix.sync.aligned.m8n8.x4.shared.b16 {%0,%1,%2,%3}, [%4];" \
        : "=r"((r)[0]), "=r"((r)[1]), "=r"((r)[2]), "=r"((r)[3]) : "r"(addr))

#define CP_ASYNC16(dst, src) \
    asm volatile("cp.async.cg.shared.global [%0], [%1], 16;" :: "r"(dst), "l"(src))
#define CP_COMMIT() asm volatile("cp.async.commit_group;" ::: "memory")
#define CP_WAIT(N)  asm volatile("cp.async.wait_group %0;" :: "n"(N) : "memory")

__global__ __launch_bounds__(NTHR, 2) void k_gemm_sim() {
    constexpr int Kd = 512, Nc = 1024, NCH = Kd / BK;
    const __half* __restrict__ pA = g_x16;
    const __half* __restrict__ pB = g_p16;
    float* __restrict__ C = g_sim;

    extern __shared__ __align__(16) char smem[];
    uint32_t sb = (uint32_t)__cvta_generic_to_shared(smem);
    #define SOFF(b, i) ((b) * 2 * MAT_BYTES + (i) * MAT_BYTES)

    int tid = threadIdx.x, lane = tid & 31, wid = tid >> 5;
    int warp_m = wid & 1, warp_n = wid >> 1;
    int m0 = blockIdx.y * BM, n0 = blockIdx.x * BN;

    float acc[4][8][4];
    #pragma unroll
    for (int i = 0; i < 4; i++)
        #pragma unroll
        for (int j = 0; j < 8; j++)
            #pragma unroll
            for (int q = 0; q < 4; q++) acc[i][j][q] = 0.0f;

    int la = (lane & 15) * PADROW + ((lane >> 4) << 3);
    int lb = (((lane >> 4) << 3) + (lane & 7)) * PADROW + (((lane >> 3) & 1) << 3);

    #define ISSUE_CHUNK(ch, b) do { \
        _Pragma("unroll") \
        for (int l = 0; l < 8; l++) { \
            int idx = tid + l * NTHR; \
            int r = idx >> 3, ko = (idx & 7) * 8; \
            size_t ga = (size_t)(m0 + r) * Kd + (ch) * BK + ko; \
            size_t gb = (size_t)(n0 + r) * Kd + (ch) * BK + ko; \
            uint32_t so = (uint32_t)((r * PADROW + ko) * 2); \
            CP_ASYNC16(sb + SOFF(b, 0) + so, pA + ga); \
            CP_ASYNC16(sb + SOFF(b, 1) + so, pB + gb); \
        } \
        CP_COMMIT(); } while (0)

    ISSUE_CHUNK(0, 0);

    #pragma unroll 1
    for (int ch = 0; ch < NCH; ch++) {
        int b = ch & 1;
        if (ch + 1 < NCH) { ISSUE_CHUNK(ch + 1, b ^ 1); CP_WAIT(1); }
        else              { CP_WAIT(0); }
        __syncthreads();

        uint32_t uA = sb + SOFF(b, 0), uB = sb + SOFF(b, 1);

        #pragma unroll
        for (int kk = 0; kk < 4; kk++) {
            int kb = kk * 16;
            uint32_t a[4][4], bfr[4][4];
            #pragma unroll
            for (int mt = 0; mt < 4; mt++) {
                uint32_t ao = 2u * ((warp_m * 64 + mt * 16) * PADROW + la + kb);
                LDSM_X4(a[mt], uA + ao);
            }
            #pragma unroll
            for (int p = 0; p < 4; p++) {
                uint32_t bo = 2u * ((warp_n * 64 + p * 16) * PADROW + lb + kb);
                LDSM_X4(bfr[p], uB + bo);
            }
            #pragma unroll
            for (int mt = 0; mt < 4; mt++)
                #pragma unroll
                for (int nt = 0; nt < 8; nt++)
                    MMA_F16(acc[mt][nt], a[mt], &bfr[nt >> 1][(nt & 1) * 2]);
        }

        if (ch + 1 < NCH) __syncthreads();
    }

    #pragma unroll
    for (int mt = 0; mt < 4; mt++) {
        int row = m0 + warp_m * 64 + mt * 16 + (lane >> 2);
        #pragma unroll
        for (int nt = 0; nt < 8; nt++) {
            int col = n0 + warp_n * 64 + nt * 8 + (lane & 3) * 2;
            *(float2*)(C + (size_t)row * Nc + col) =
                make_float2(acc[mt][nt][0], acc[mt][nt][1]);
            *(float2*)(C + (size_t)(row + 8) * Nc + col) =
                make_float2(acc[mt][nt][2], acc[mt][nt][3]);
        }
    }
    #undef SOFF
}

// ============ fused gumbel-softmax + sparse pt: one block (256 thr) per row ============
// (R10 version — measured fastest across 5 restructuring attempts.)
// w = softmax((sim+g)/tau); pt[row] = sum_k w_k * p16[k] over w > WTH (~5 entries).
// Overflow (>CAP survivors) falls back to the exact full 1024-term sum from smem.
__global__ void k_softmax_pt(const float* __restrict__ u, float* __restrict__ out_pt) {
    int row = blockIdx.x, t = threadIdx.x, lane = t & 31, wid = t >> 5;
    size_t base = (size_t)row * CLS;

    __shared__ float  s_w[CLS];
    __shared__ unsigned short s_idx[CAP];
    __shared__ float  red[8];
    __shared__ float  red2[8][2];
    __shared__ int    s_wbase[8], s_total;

    float4 s4 = ((const float4*)(g_sim + base))[t];
    float4 u4 = ((const float4*)(u + base))[t];

    float l[4];
    l[0] = (s4.x - __logf(-__logf(u4.x))) * INV_TAU;
    l[1] = (s4.y - __logf(-__logf(u4.y))) * INV_TAU;
    l[2] = (s4.z - __logf(-__logf(u4.z))) * INV_TAU;
    l[3] = (s4.w - __logf(-__logf(u4.w))) * INV_TAU;

    float mx = fmaxf(fmaxf(l[0], l[1]), fmaxf(l[2], l[3]));
    #pragma unroll
    for (int o = 16; o; o >>= 1) mx = fmaxf(mx, __shfl_xor_sync(0xffffffffu, mx, o));
    if (lane == 0) red[wid] = mx;
    __syncthreads();
    mx = red[0];
    #pragma unroll
    for (int i = 1; i < 8; i++) mx = fmaxf(mx, red[i]);

    float e[4];
    e[0] = __expf(l[0] - mx); e[1] = __expf(l[1] - mx);
    e[2] = __expf(l[2] - mx); e[3] = __expf(l[3] - mx);
    float sum = e[0] + e[1] + e[2] + e[3];
    float dot = e[0] * s4.x + e[1] * s4.y + e[2] * s4.z + e[3] * s4.w;
    #pragma unroll
    for (int o = 16; o; o >>= 1) {
        sum += __shfl_xor_sync(0xffffffffu, sum, o);
        dot += __shfl_xor_sync(0xffffffffu, dot, o);
    }
    if (lane == 0) { red2[wid][0] = sum; red2[wid][1] = dot; }
    __syncthreads();
    float tsum = 0.f, tdot = 0.f;
    #pragma unroll
    for (int i = 0; i < 8; i++) { tsum += red2[i][0]; tdot += red2[i][1]; }
    float inv = 1.0f / tsum;

    float w[4];
    #pragma unroll
    for (int i = 0; i < 4; i++) w[i] = e[i] * inv;
    *(float4*)(s_w + 4 * t) = make_float4(w[0], w[1], w[2], w[3]);

    // ---- compact indices of w > WTH via warp scan ----
    int c = (w[0] > WTH) + (w[1] > WTH) + (w[2] > WTH) + (w[3] > WTH);
    int sc = c;
    #pragma unroll
    for (int o = 1; o < 32; o <<= 1) {
        int v = __shfl_up_sync(0xffffffffu, sc, o);
        if (lane >= o) sc += v;
    }
    int excl = sc - c;
    if (lane == 31) s_wbase[wid] = sc;          // warp total (temp)
    __syncthreads();
    if (t == 0) {
        int run = 0;
        #pragma unroll
        for (int i = 0; i < 8; i++) { int v = s_wbase[i]; s_wbase[i] = run; run += v; }
        s_total = run;
    }
    __syncthreads();
    int total = s_total;
    if (total <= CAP) {
        int pos = s_wbase[wid] + excl;
        #pragma unroll
        for (int i = 0; i < 4; i++)
            if (w[i] > WTH) s_idx[pos++] = (unsigned short)(4 * t + i);
    }
    __syncthreads();

    // ---- sparse pt accumulation: each thread owns cols [2t, 2t+1] ----
    float ax = 0.f, ay = 0.f;
    int c2 = 2 * t;
    if (total <= CAP) {
        #pragma unroll 2
        for (int j = 0; j < total; j++) {
            int k = s_idx[j];
            float wv = s_w[k];
            __half2 pv = *(const __half2*)(g_p16 + (size_t)k * DIM + c2);
            float2 pf = __half22float2(pv);
            ax += wv * pf.x; ay += wv * pf.y;
        }
    } else {
        #pragma unroll 4
        for (int k = 0; k < CLS; k++) {
            float wv = s_w[k];
            __half2 pv = *(const __half2*)(g_p16 + (size_t)k * DIM + c2);
            float2 pf = __half22float2(pv);
            ax += wv * pf.x; ay += wv * pf.y;
        }
    }
    *(float2*)(out_pt + (size_t)row * DIM + c2) = make_float2(ax, ay);

    if (t == 0) atomicAdd(&g_acc[2], (double)(tdot * inv));
}

// ---- finalize: div_loss = ||sum_k p_k||^2 - 1024 (rows are unit-norm) ----
__global__ void k_finalize(float* __restrict__ outs) {
    int t = threadIdx.x;                   // 512 threads = one column each
    double cs = g_colsum[t];
    double v = cs * cs;
    #pragma unroll
    for (int o = 16; o; o >>= 1) v += __shfl_xor_sync(0xffffffffu, v, o);
    __shared__ double sm[16];
    if ((t & 31) == 0) sm[t >> 5] = v;
    __syncthreads();
    if (t < 32) {
        double x = (t < 16) ? sm[t] : 0.0;
        #pragma unroll
        for (int o = 16; o; o >>= 1) x += __shfl_xor_sync(0xffffffffu, x, o);
        if (t == 0) {
            outs[0] = (float)(1.0 - g_acc[2] / (double)BATCH);  // sim_loss
            outs[1] = (float)(x - (double)CLS);                 // div_loss
        }
    }
}

extern "C" void kernel_launch(void* const* d_in, const int* in_sizes, int n_in,
                              void* d_out, int out_size) {
    const float* input  = (const float*)d_in[0];   // [16384, 512]
    const float* protos = (const float*)d_in[1];   // [1024, 512]
    const float* gu     = (const float*)d_in[2];   // [16384, 1024]
    float* out = (float*)d_out;
    float* out_pt = out;                                            // [16384, 512]
    float* out_p  = out + (size_t)BATCH * DIM;                      // [1024, 512]
    float* out_sc = out + (size_t)BATCH * DIM + (size_t)CLS * DIM;  // 2 scalars

    cudaFuncSetAttribute(k_gemm_sim, cudaFuncAttributeMaxDynamicSharedMemorySize, GSMEM_SZ);

    // order chosen so k_softmax_pt is launch #4 (the one ncu captures):
    k_norm_x<<<BATCH, 128>>>(input);                                // #1 (+ scratch init)
    k_norm_p<<<CLS, 128>>>(protos, out_p);                          // #2
    k_gemm_sim<<<dim3(CLS / BN, BATCH / BM), NTHR, GSMEM_SZ>>>();   // #3  sim
    k_softmax_pt<<<BATCH, 256>>>(gu, out_pt);                       // #4  softmax + pt
    k_proto_stats<<<dim3(4, 64), 128>>>(out_p);                     // #5  (independent)
    k_finalize<<<1, 512>>>(out_sc);                                 // #6
}